// round 1
// baseline (speedup 1.0000x reference)
#include <cuda_runtime.h>
#include <cuda_bf16.h>

// YOLOv1 loss kernel.
// Per cell (N*7*7 cells, 30 channels): build 2 predicted boxes + target box,
// IOU-select best box, accumulate 5 weighted SE terms. Sum all cells, /N.
//
// Stage 1: blocks of 128 threads each handle 128 cells. Cooperative fully
//          coalesced float4 loads of p/t tiles into SMEM, per-thread cell
//          compute, deterministic block tree-reduce in double -> g_partials.
// Stage 2: single block folds partials, writes float scalar to d_out.

#define CELLS_PER_BLOCK 128
#define CH 30

static __device__ double g_partials[8192];

__device__ __forceinline__ float iou_f(float ax1, float ay1, float ax2, float ay2,
                                       float bx1, float by1, float bx2, float by2) {
    float xl = fmaxf(ax1, bx1);
    float yt = fmaxf(ay1, by1);
    float xr = fminf(ax2, bx2);
    float yb = fminf(ay2, by2);
    float ix = fmaxf(xr - xl, 0.0f);
    float iy = fmaxf(yb - yt, 0.0f);
    float inter = ix * iy;
    float aa = fabsf((ax2 - ax1) * (ay2 - ay1));
    float ba = fabsf((bx2 - bx1) * (by2 - by1));
    return inter / (aa + ba - inter + 1e-7f);
}

__device__ __forceinline__ float sgn_sqrt(float x) {
    // sign(x)*sqrt(|x|); sign(0)=0 matches since sqrt(0)=0
    float s = sqrtf(fabsf(x));
    return (x > 0.0f) ? s : ((x < 0.0f) ? -s : 0.0f);
}

__global__ void __launch_bounds__(CELLS_PER_BLOCK)
yolo_loss_main(const float* __restrict__ p_g, const float* __restrict__ t_g,
               int totalCells) {
    __shared__ float p_s[CELLS_PER_BLOCK * CH];
    __shared__ float t_s[CELLS_PER_BLOCK * CH];
    __shared__ double warp_s[CELLS_PER_BLOCK / 32];

    const int tid = threadIdx.x;
    const int cell0 = blockIdx.x * CELLS_PER_BLOCK;
    const int nCells = min(CELLS_PER_BLOCK, totalCells - cell0);
    const int nFloats = nCells * CH;

    // --- coalesced staging (base offset cell0*30*4B = blockIdx*15360B, 16B aligned) ---
    {
        const float4* pg4 = reinterpret_cast<const float4*>(p_g + (size_t)cell0 * CH);
        const float4* tg4 = reinterpret_cast<const float4*>(t_g + (size_t)cell0 * CH);
        float4* ps4 = reinterpret_cast<float4*>(p_s);
        float4* ts4 = reinterpret_cast<float4*>(t_s);
        const int nf4 = nFloats >> 2;
        #pragma unroll 4
        for (int i = tid; i < nf4; i += CELLS_PER_BLOCK) {
            ps4[i] = pg4[i];
            ts4[i] = tg4[i];
        }
        // scalar tail (only on a ragged last block; nCells*30 % 4 may be 2)
        for (int i = (nf4 << 2) + tid; i < nFloats; i += CELLS_PER_BLOCK) {
            p_s[i] = p_g[(size_t)cell0 * CH + i];
            t_s[i] = t_g[(size_t)cell0 * CH + i];
        }
    }
    __syncthreads();

    double acc = 0.0;
    if (tid < nCells) {
        const float* p = &p_s[tid * CH];
        const float* t = &t_s[tid * CH];

        const int cell = cell0 + tid;
        const int rc = cell % 49;
        const float lty = (float)(rc / 7) / 7.0f; // row index i
        const float ltx = (float)(rc % 7) / 7.0f; // col index j

        const float t4 = t[4];
        const float coordf = (t4 > 0.0f) ? 1.0f : 0.0f;
        const float noobjf = (t4 == 0.0f) ? 1.0f : 0.0f;

        // predicted box 1
        float b1x1 = ltx + p[0] / 7.0f - p[2] * 0.5f;
        float b1y1 = lty + p[1] / 7.0f - p[3] * 0.5f;
        float b1x2 = p[2] + b1x1;
        float b1y2 = p[3] + b1y1;
        // predicted box 2 (faithful to reference: p[5:7]*(1/S - 0.5))
        const float c2 = (1.0f / 7.0f) - 0.5f;
        float b2x1 = ltx + p[5] * c2;
        float b2y1 = lty + p[6] * c2;
        float b2x2 = p[7] + b2x1;
        float b2y2 = p[8] + b2y1;
        // target box
        float tbx1 = ltx + t[0] / 7.0f - t[2] * 0.5f;
        float tby1 = lty + t[1] / 7.0f - t[3] * 0.5f;
        float tbx2 = t[2] + tbx1;
        float tby2 = t[3] + tby1;

        float iou1 = iou_f(b1x1, b1y1, b1x2, b1y2, tbx1, tby1, tbx2, tby2);
        float iou2 = iou_f(b2x1, b2y1, b2x2, b2y2, tbx1, tby1, tbx2, tby2);
        bool sel = (iou1 >= iou2);

        float bx0 = sel ? p[0] : p[5];
        float bx1 = sel ? p[1] : p[6];
        float bx2 = sel ? p[2] : p[7];
        float bx3 = sel ? p[3] : p[8];
        float bx4 = sel ? p[4] : p[9];

        float dx = bx0 - t[0];
        float dy = bx1 - t[1];
        float lxy = dx * dx + dy * dy;

        float dw = sgn_sqrt(bx2) - sqrtf(t[2]);
        float dh = sgn_sqrt(bx3) - sqrtf(t[3]);
        float lwh = dw * dw + dh * dh;

        float dob = fmaxf(iou1, iou2) - bx4;
        float lobj = dob * dob;

        float dn1 = p[4] - t[4];
        float dn2 = p[9] - t[9];
        float lnoobj = dn1 * dn1 + dn2 * dn2;

        float llab = 0.0f;
        #pragma unroll
        for (int k = 10; k < 30; k++) {
            float d = p[k] - t[k];
            llab += d * d;
        }

        float cell_loss = coordf * (5.0f * (lxy + lwh) + lobj + llab)
                        + 0.5f * noobjf * lnoobj;
        acc = (double)cell_loss;
    }

    // deterministic block reduction in double
    #pragma unroll
    for (int o = 16; o > 0; o >>= 1)
        acc += __shfl_down_sync(0xFFFFFFFFu, acc, o);
    if ((tid & 31) == 0) warp_s[tid >> 5] = acc;
    __syncthreads();
    if (tid < (CELLS_PER_BLOCK / 32)) {
        double v = warp_s[tid];
        #pragma unroll
        for (int o = (CELLS_PER_BLOCK / 64); o > 0; o >>= 1)
            v += __shfl_down_sync(0xFFFFFFFFu, v, o);
        if (tid == 0) g_partials[blockIdx.x] = v;
    }
}

__global__ void __launch_bounds__(1024)
yolo_loss_reduce(float* __restrict__ out, int nparts, float inv_batch) {
    __shared__ double s[32];
    const int tid = threadIdx.x;
    double v = 0.0;
    for (int i = tid; i < nparts; i += 1024) v += g_partials[i];
    #pragma unroll
    for (int o = 16; o > 0; o >>= 1)
        v += __shfl_down_sync(0xFFFFFFFFu, v, o);
    if ((tid & 31) == 0) s[tid >> 5] = v;
    __syncthreads();
    if (tid < 32) {
        double w = s[tid];
        #pragma unroll
        for (int o = 16; o > 0; o >>= 1)
            w += __shfl_down_sync(0xFFFFFFFFu, w, o);
        if (tid == 0) out[0] = (float)(w * (double)inv_batch);
    }
}

extern "C" void kernel_launch(void* const* d_in, const int* in_sizes, int n_in,
                              void* d_out, int out_size) {
    const float* p = (const float*)d_in[0]; // modely [N,7,7,30]
    const float* t = (const float*)d_in[1]; // targety [N,7,7,30]
    float* out = (float*)d_out;

    const int totalCells = in_sizes[0] / CH;      // N*49
    const int nbatch = totalCells / 49;           // N
    const int nblocks = (totalCells + CELLS_PER_BLOCK - 1) / CELLS_PER_BLOCK;

    yolo_loss_main<<<nblocks, CELLS_PER_BLOCK>>>(p, t, totalCells);
    yolo_loss_reduce<<<1, 1024>>>(out, nblocks, 1.0f / (float)nbatch);
}

// round 2
// speedup vs baseline: 1.0702x; 1.0702x over previous
#include <cuda_runtime.h>
#include <cuda_bf16.h>

// YOLOv1 loss, single fused kernel.
// Blocks of 128 threads each handle 128 cells (30 ch/cell). Cooperative
// coalesced float4 staging into SMEM, per-thread cell compute, deterministic
// block tree-reduce in double -> g_partials. Last block to finish (threadfence
// + atomic counter) folds all partials in fixed index order and writes the
// scalar. Counter is reset every launch -> graph-replay deterministic.

#define CELLS_PER_BLOCK 128
#define CH 30
#define MAX_BLOCKS 8192

static __device__ double g_partials[MAX_BLOCKS];
static __device__ unsigned int g_arrived; // zero-init; reset to 0 at end of each launch

__device__ __forceinline__ float iou_f(float ax1, float ay1, float ax2, float ay2,
                                       float bx1, float by1, float bx2, float by2) {
    float xl = fmaxf(ax1, bx1);
    float yt = fmaxf(ay1, by1);
    float xr = fminf(ax2, bx2);
    float yb = fminf(ay2, by2);
    float ix = fmaxf(xr - xl, 0.0f);
    float iy = fmaxf(yb - yt, 0.0f);
    float inter = ix * iy;
    float aa = fabsf((ax2 - ax1) * (ay2 - ay1));
    float ba = fabsf((bx2 - bx1) * (by2 - by1));
    return inter / (aa + ba - inter + 1e-7f);
}

__device__ __forceinline__ float sgn_sqrt(float x) {
    float s = sqrtf(fabsf(x));
    return (x > 0.0f) ? s : ((x < 0.0f) ? -s : 0.0f);
}

__global__ void __launch_bounds__(CELLS_PER_BLOCK)
yolo_loss_fused(const float* __restrict__ p_g, const float* __restrict__ t_g,
                float* __restrict__ out, int totalCells, float inv_batch) {
    __shared__ float p_s[CELLS_PER_BLOCK * CH];
    __shared__ float t_s[CELLS_PER_BLOCK * CH];
    __shared__ double warp_s[CELLS_PER_BLOCK / 32];
    __shared__ int s_is_last;

    const int tid = threadIdx.x;
    const int cell0 = blockIdx.x * CELLS_PER_BLOCK;
    const int nCells = min(CELLS_PER_BLOCK, totalCells - cell0);
    const int nFloats = nCells * CH;

    // --- coalesced staging (base offset cell0*30*4B = blockIdx*15360B, 16B aligned) ---
    {
        const float4* pg4 = reinterpret_cast<const float4*>(p_g + (size_t)cell0 * CH);
        const float4* tg4 = reinterpret_cast<const float4*>(t_g + (size_t)cell0 * CH);
        float4* ps4 = reinterpret_cast<float4*>(p_s);
        float4* ts4 = reinterpret_cast<float4*>(t_s);
        const int nf4 = nFloats >> 2;
        #pragma unroll 4
        for (int i = tid; i < nf4; i += CELLS_PER_BLOCK) {
            ps4[i] = pg4[i];
            ts4[i] = tg4[i];
        }
        for (int i = (nf4 << 2) + tid; i < nFloats; i += CELLS_PER_BLOCK) {
            p_s[i] = p_g[(size_t)cell0 * CH + i];
            t_s[i] = t_g[(size_t)cell0 * CH + i];
        }
    }
    __syncthreads();

    double acc = 0.0;
    if (tid < nCells) {
        const float* p = &p_s[tid * CH];
        const float* t = &t_s[tid * CH];

        const int cell = cell0 + tid;
        const int rc = cell % 49;
        const float lty = (float)(rc / 7) * (1.0f / 7.0f);
        const float ltx = (float)(rc % 7) * (1.0f / 7.0f);

        const float t4 = t[4];
        const float coordf = (t4 > 0.0f) ? 1.0f : 0.0f;
        const float noobjf = (t4 == 0.0f) ? 1.0f : 0.0f;

        // predicted box 1
        float b1x1 = ltx + p[0] * (1.0f / 7.0f) - p[2] * 0.5f;
        float b1y1 = lty + p[1] * (1.0f / 7.0f) - p[3] * 0.5f;
        float b1x2 = p[2] + b1x1;
        float b1y2 = p[3] + b1y1;
        // predicted box 2 (faithful to reference: p[5:7]*(1/S - 0.5))
        const float c2 = (1.0f / 7.0f) - 0.5f;
        float b2x1 = ltx + p[5] * c2;
        float b2y1 = lty + p[6] * c2;
        float b2x2 = p[7] + b2x1;
        float b2y2 = p[8] + b2y1;
        // target box
        float tbx1 = ltx + t[0] * (1.0f / 7.0f) - t[2] * 0.5f;
        float tby1 = lty + t[1] * (1.0f / 7.0f) - t[3] * 0.5f;
        float tbx2 = t[2] + tbx1;
        float tby2 = t[3] + tby1;

        float iou1 = iou_f(b1x1, b1y1, b1x2, b1y2, tbx1, tby1, tbx2, tby2);
        float iou2 = iou_f(b2x1, b2y1, b2x2, b2y2, tbx1, tby1, tbx2, tby2);
        bool sel = (iou1 >= iou2);

        float bx0 = sel ? p[0] : p[5];
        float bx1 = sel ? p[1] : p[6];
        float bx2 = sel ? p[2] : p[7];
        float bx3 = sel ? p[3] : p[8];
        float bx4 = sel ? p[4] : p[9];

        float dx = bx0 - t[0];
        float dy = bx1 - t[1];
        float lxy = dx * dx + dy * dy;

        float dw = sgn_sqrt(bx2) - sqrtf(t[2]);
        float dh = sgn_sqrt(bx3) - sqrtf(t[3]);
        float lwh = dw * dw + dh * dh;

        float dob = fmaxf(iou1, iou2) - bx4;
        float lobj = dob * dob;

        float dn1 = p[4] - t[4];
        float dn2 = p[9] - t[9];
        float lnoobj = dn1 * dn1 + dn2 * dn2;

        float llab = 0.0f;
        #pragma unroll
        for (int k = 10; k < 30; k++) {
            float d = p[k] - t[k];
            llab += d * d;
        }

        float cell_loss = coordf * (5.0f * (lxy + lwh) + lobj + llab)
                        + 0.5f * noobjf * lnoobj;
        acc = (double)cell_loss;
    }

    // deterministic block reduction in double
    #pragma unroll
    for (int o = 16; o > 0; o >>= 1)
        acc += __shfl_down_sync(0xFFFFFFFFu, acc, o);
    if ((tid & 31) == 0) warp_s[tid >> 5] = acc;
    __syncthreads();
    if (tid == 0) {
        double v = warp_s[0] + warp_s[1] + warp_s[2] + warp_s[3];
        g_partials[blockIdx.x] = v;
        __threadfence();
        unsigned int old = atomicAdd(&g_arrived, 1u);
        s_is_last = (old == gridDim.x - 1) ? 1 : 0;
    }
    __syncthreads();

    // last block folds all partials in fixed index order (deterministic)
    if (s_is_last) {
        const int nparts = gridDim.x;
        double v = 0.0;
        for (int i = tid; i < nparts; i += CELLS_PER_BLOCK)
            v += g_partials[i];
        #pragma unroll
        for (int o = 16; o > 0; o >>= 1)
            v += __shfl_down_sync(0xFFFFFFFFu, v, o);
        if ((tid & 31) == 0) warp_s[tid >> 5] = v;
        __syncthreads();
        if (tid == 0) {
            double w = warp_s[0] + warp_s[1] + warp_s[2] + warp_s[3];
            out[0] = (float)(w * (double)inv_batch);
            g_arrived = 0; // reset for next launch / graph replay
        }
    }
}

extern "C" void kernel_launch(void* const* d_in, const int* in_sizes, int n_in,
                              void* d_out, int out_size) {
    const float* p = (const float*)d_in[0]; // modely [N,7,7,30]
    const float* t = (const float*)d_in[1]; // targety [N,7,7,30]
    float* out = (float*)d_out;

    const int totalCells = in_sizes[0] / CH; // N*49
    const int nbatch = totalCells / 49;      // N
    int nblocks = (totalCells + CELLS_PER_BLOCK - 1) / CELLS_PER_BLOCK;
    if (nblocks > MAX_BLOCKS) nblocks = MAX_BLOCKS; // 8192*49/128 = 3136, fits

    yolo_loss_fused<<<nblocks, CELLS_PER_BLOCK>>>(p, t, out, totalCells,
                                                  1.0f / (float)nbatch);
}

// round 3
// speedup vs baseline: 1.5920x; 1.4877x over previous
#include <cuda_runtime.h>
#include <cuda_bf16.h>
#include <cstdint>

// YOLOv1 loss — persistent blocks + double-buffered cp.async.bulk pipeline.
// Tile = 128 cells (15360 B per array). Stage s holds tile data for p and t;
// one mbarrier per stage with expect_tx = 30720. Thread 0 issues next tile's
// bulk copies while all threads compute the current tile out of SMEM.
// Deterministic: per-block accumulation in fixed tile order (double), last
// block (threadfence+counter) folds partials in fixed index order.

#define CPB 128                      // cells per tile == threads per block
#define CH 30
#define TILE_FLOATS (CPB * CH)       // 3840
#define TILE_BYTES  (TILE_FLOATS * 4) // 15360
#define STAGE_BYTES (2 * TILE_BYTES)  // 30720 (p + t)
#define MAXG 4096

static __device__ double g_partials[MAXG];
static __device__ unsigned int g_arrived;

__device__ __forceinline__ uint32_t smem_u32(const void* p) {
    uint32_t a;
    asm("{ .reg .u64 t; cvta.to.shared.u64 t, %1; cvt.u32.u64 %0, t; }"
        : "=r"(a) : "l"(p));
    return a;
}

__device__ __forceinline__ void mbar_init(uint32_t mb, uint32_t cnt) {
    asm volatile("mbarrier.init.shared.b64 [%0], %1;" :: "r"(mb), "r"(cnt) : "memory");
}

__device__ __forceinline__ void mbar_expect_tx(uint32_t mb, uint32_t bytes) {
    asm volatile("mbarrier.arrive.expect_tx.shared.b64 _, [%0], %1;"
                 :: "r"(mb), "r"(bytes) : "memory");
}

__device__ __forceinline__ void bulk_g2s(uint32_t dst, const void* src,
                                         uint32_t bytes, uint32_t mb) {
    asm volatile(
        "cp.async.bulk.shared::cluster.global.mbarrier::complete_tx::bytes "
        "[%0], [%1], %2, [%3];"
        :: "r"(dst), "l"(src), "r"(bytes), "r"(mb) : "memory");
}

__device__ __forceinline__ void mbar_wait(uint32_t mb, uint32_t parity) {
    uint32_t done = 0;
    while (!done) {
        asm volatile(
            "{\n\t.reg .pred p;\n\t"
            "mbarrier.try_wait.parity.shared.b64 p, [%1], %2, 0x989680;\n\t"
            "selp.b32 %0, 1, 0, p;\n\t}"
            : "=r"(done) : "r"(mb), "r"(parity) : "memory");
    }
}

__device__ __forceinline__ float iou_f(float ax1, float ay1, float ax2, float ay2,
                                       float bx1, float by1, float bx2, float by2) {
    float xl = fmaxf(ax1, bx1);
    float yt = fmaxf(ay1, by1);
    float xr = fminf(ax2, bx2);
    float yb = fminf(ay2, by2);
    float ix = fmaxf(xr - xl, 0.0f);
    float iy = fmaxf(yb - yt, 0.0f);
    float inter = ix * iy;
    float aa = fabsf((ax2 - ax1) * (ay2 - ay1));
    float ba = fabsf((bx2 - bx1) * (by2 - by1));
    return inter / (aa + ba - inter + 1e-7f);
}

__device__ __forceinline__ float sgn_sqrt(float x) {
    float s = sqrtf(fabsf(x));
    return (x > 0.0f) ? s : ((x < 0.0f) ? -s : 0.0f);
}

// Loss for one cell. p, t: 30 floats each. rc = cell % 49.
__device__ __forceinline__ float cell_loss(const float* __restrict__ p,
                                           const float* __restrict__ t, int rc) {
    const float lty = (float)(rc / 7) * (1.0f / 7.0f);
    const float ltx = (float)(rc % 7) * (1.0f / 7.0f);

    const float t4 = t[4];
    const float coordf = (t4 > 0.0f) ? 1.0f : 0.0f;
    const float noobjf = (t4 == 0.0f) ? 1.0f : 0.0f;

    float b1x1 = ltx + p[0] * (1.0f / 7.0f) - p[2] * 0.5f;
    float b1y1 = lty + p[1] * (1.0f / 7.0f) - p[3] * 0.5f;
    float b1x2 = p[2] + b1x1;
    float b1y2 = p[3] + b1y1;
    const float c2 = (1.0f / 7.0f) - 0.5f;   // faithful to reference bug
    float b2x1 = ltx + p[5] * c2;
    float b2y1 = lty + p[6] * c2;
    float b2x2 = p[7] + b2x1;
    float b2y2 = p[8] + b2y1;
    float tbx1 = ltx + t[0] * (1.0f / 7.0f) - t[2] * 0.5f;
    float tby1 = lty + t[1] * (1.0f / 7.0f) - t[3] * 0.5f;
    float tbx2 = t[2] + tbx1;
    float tby2 = t[3] + tby1;

    float iou1 = iou_f(b1x1, b1y1, b1x2, b1y2, tbx1, tby1, tbx2, tby2);
    float iou2 = iou_f(b2x1, b2y1, b2x2, b2y2, tbx1, tby1, tbx2, tby2);
    bool sel = (iou1 >= iou2);

    float bx0 = sel ? p[0] : p[5];
    float bx1 = sel ? p[1] : p[6];
    float bx2 = sel ? p[2] : p[7];
    float bx3 = sel ? p[3] : p[8];
    float bx4 = sel ? p[4] : p[9];

    float dx = bx0 - t[0];
    float dy = bx1 - t[1];
    float lxy = dx * dx + dy * dy;

    float dw = sgn_sqrt(bx2) - sqrtf(t[2]);
    float dh = sgn_sqrt(bx3) - sqrtf(t[3]);
    float lwh = dw * dw + dh * dh;

    float dob = fmaxf(iou1, iou2) - bx4;
    float lobj = dob * dob;

    float dn1 = p[4] - t[4];
    float dn2 = p[9] - t[9];
    float lnoobj = dn1 * dn1 + dn2 * dn2;

    float llab = 0.0f;
    #pragma unroll
    for (int k = 10; k < 30; k++) {
        float d = p[k] - t[k];
        llab += d * d;
    }

    return coordf * (5.0f * (lxy + lwh) + lobj + llab) + 0.5f * noobjf * lnoobj;
}

__global__ void __launch_bounds__(CPB, 3)
yolo_loss_pipe(const float* __restrict__ p_g, const float* __restrict__ t_g,
               float* __restrict__ out, int totalCells, float inv_batch,
               int nFull) {
    extern __shared__ float smem[];
    float* pbuf = smem;                      // [2][TILE_FLOATS]
    float* tbuf = smem + 2 * TILE_FLOATS;    // [2][TILE_FLOATS]

    __shared__ __align__(8) uint64_t mbar_store[2];
    __shared__ double warp_s[CPB / 32];
    __shared__ int s_is_last;

    const int tid = threadIdx.x;
    const int B = gridDim.x;
    const uint32_t mb0 = smem_u32(&mbar_store[0]);
    const uint32_t mb1 = smem_u32(&mbar_store[1]);
    const uint32_t pbuf_a = smem_u32(pbuf);
    const uint32_t tbuf_a = smem_u32(tbuf);

    if (tid == 0) { mbar_init(mb0, 1); mbar_init(mb1, 1); }
    __syncthreads();

    // prologue: prefetch first tile into stage 0
    if (tid == 0 && (int)blockIdx.x < nFull) {
        mbar_expect_tx(mb0, STAGE_BYTES);
        bulk_g2s(pbuf_a, p_g + (size_t)blockIdx.x * TILE_FLOATS, TILE_BYTES, mb0);
        bulk_g2s(tbuf_a, t_g + (size_t)blockIdx.x * TILE_FLOATS, TILE_BYTES, mb0);
    }

    double acc = 0.0;
    uint32_t ph0 = 0, ph1 = 0;
    int it = 0;
    for (int tile = blockIdx.x; tile < nFull; tile += B, it++) {
        const int st = it & 1;
        const uint32_t mb = st ? mb1 : mb0;

        // issue next tile into the other stage (free since last iter's barrier)
        const int nxt = tile + B;
        if (tid == 0 && nxt < nFull) {
            const uint32_t mbn = st ? mb0 : mb1;
            const uint32_t off = (st ^ 1) * TILE_FLOATS;
            mbar_expect_tx(mbn, STAGE_BYTES);
            bulk_g2s(pbuf_a + off * 4, p_g + (size_t)nxt * TILE_FLOATS, TILE_BYTES, mbn);
            bulk_g2s(tbuf_a + off * 4, t_g + (size_t)nxt * TILE_FLOATS, TILE_BYTES, mbn);
        }

        // wait current stage
        if (st) { mbar_wait(mb, ph1); ph1 ^= 1; }
        else    { mbar_wait(mb, ph0); ph0 ^= 1; }

        const float* p = pbuf + st * TILE_FLOATS + tid * CH;
        const float* t = tbuf + st * TILE_FLOATS + tid * CH;
        const int cell = tile * CPB + tid;
        acc += (double)cell_loss(p, t, cell % 49);

        __syncthreads();  // stage free for reuse
    }

    // tail tile (ragged), handled by the block that would own tile nFull
    if (nFull * CPB < totalCells && (nFull % B) == (int)blockIdx.x) {
        const int cell = nFull * CPB + tid;
        if (cell < totalCells) {
            float pl[CH], tl[CH];
            #pragma unroll
            for (int k = 0; k < CH; k++) {
                pl[k] = p_g[(size_t)cell * CH + k];
                tl[k] = t_g[(size_t)cell * CH + k];
            }
            acc += (double)cell_loss(pl, tl, cell % 49);
        }
    }

    // deterministic block reduction (double)
    #pragma unroll
    for (int o = 16; o > 0; o >>= 1)
        acc += __shfl_down_sync(0xFFFFFFFFu, acc, o);
    if ((tid & 31) == 0) warp_s[tid >> 5] = acc;
    __syncthreads();
    if (tid == 0) {
        double v = warp_s[0] + warp_s[1] + warp_s[2] + warp_s[3];
        g_partials[blockIdx.x] = v;
        __threadfence();
        unsigned int old = atomicAdd(&g_arrived, 1u);
        s_is_last = (old == gridDim.x - 1) ? 1 : 0;
    }
    __syncthreads();

    if (s_is_last) {
        const int nparts = gridDim.x;
        double v = 0.0;
        for (int i = tid; i < nparts; i += CPB)
            v += g_partials[i];
        #pragma unroll
        for (int o = 16; o > 0; o >>= 1)
            v += __shfl_down_sync(0xFFFFFFFFu, v, o);
        if ((tid & 31) == 0) warp_s[tid >> 5] = v;
        __syncthreads();
        if (tid == 0) {
            double w = warp_s[0] + warp_s[1] + warp_s[2] + warp_s[3];
            out[0] = (float)(w * (double)inv_batch);
            g_arrived = 0;  // reset for next launch / graph replay
        }
    }
}

extern "C" void kernel_launch(void* const* d_in, const int* in_sizes, int n_in,
                              void* d_out, int out_size) {
    const float* p = (const float*)d_in[0];  // modely [N,7,7,30]
    const float* t = (const float*)d_in[1];  // targety [N,7,7,30]
    float* out = (float*)d_out;

    const int totalCells = in_sizes[0] / CH;  // N*49
    const int nbatch = totalCells / 49;       // N
    const int nFull = totalCells / CPB;
    const int totalTiles = (totalCells + CPB - 1) / CPB;

    int nblocks = 148 * 3;                    // 3 resident blocks/SM (SMEM-limited)
    if (nblocks > totalTiles) nblocks = totalTiles;
    if (nblocks < 1) nblocks = 1;
    if (nblocks > MAXG) nblocks = MAXG;

    const int smem_bytes = 4 * TILE_FLOATS * (int)sizeof(float);  // 61440
    static bool attr_set = false;
    if (!attr_set) {
        cudaFuncSetAttribute(yolo_loss_pipe,
                             cudaFuncAttributeMaxDynamicSharedMemorySize,
                             smem_bytes);
        attr_set = true;
    }

    yolo_loss_pipe<<<nblocks, CPB, smem_bytes>>>(p, t, out, totalCells,
                                                 1.0f / (float)nbatch, nFull);
}